// round 17
// baseline (speedup 1.0000x reference)
#include <cuda_runtime.h>
#include <cuda_fp16.h>
#include <cstdint>
#include <math.h>

#define T_DIM 2048
#define B_DIM 32
#define D_DIM 512
#define M_DIM (T_DIM * B_DIM)     // 65536
#define KGL   512

// ---------------------------------------------------------------------------
// Device-global scratch
// ---------------------------------------------------------------------------
__device__ __half g_zgh[(size_t)M_DIM * 2 * D_DIM];   // [M, 2D] fp16
__device__ __half g_xh [(size_t)M_DIM * D_DIM];       // x fp16
__device__ __half g_ph [(size_t)M_DIM * D_DIM];       // proj fp16
__device__ __half g_hh [(size_t)M_DIM * D_DIM];       // h fp16
__device__ __half g_wih[2 * D_DIM * D_DIM];           // W_in  fp16
__device__ __half g_woh[D_DIM * D_DIM];               // W_out fp16

// ---------------------------------------------------------------------------
// Helpers
// ---------------------------------------------------------------------------
__device__ __forceinline__ uint32_t s2u(const void* p) {
    return (uint32_t)__cvta_generic_to_shared(p);
}
__device__ __forceinline__ uint32_t swz(uint32_t off) {
    return off ^ ((off >> 3) & 0x70);
}
__device__ __forceinline__ void cpa16(uint32_t saddr, const void* g) {
    asm volatile("cp.async.cg.shared.global [%0], [%1], 16;" :: "r"(saddr), "l"(g));
}
#define CP_COMMIT() asm volatile("cp.async.commit_group;" ::: "memory")
#define CP_WAIT1()  asm volatile("cp.async.wait_group 1;" ::: "memory")
#define CP_WAIT0()  asm volatile("cp.async.wait_group 0;" ::: "memory")

__device__ __forceinline__ void ldsm4(uint32_t& r0, uint32_t& r1,
                                      uint32_t& r2, uint32_t& r3, uint32_t a) {
    asm volatile("ldmatrix.sync.aligned.m8n8.x4.shared.b16 {%0,%1,%2,%3}, [%4];"
                 : "=r"(r0), "=r"(r1), "=r"(r2), "=r"(r3) : "r"(a));
}
__device__ __forceinline__ void mma16816h(uint32_t& c0, uint32_t& c1,
                                          uint32_t a0, uint32_t a1, uint32_t a2, uint32_t a3,
                                          uint32_t b0, uint32_t b1) {
    asm volatile(
        "mma.sync.aligned.m16n8k16.row.col.f16.f16.f16.f16 "
        "{%0,%1}, {%2,%3,%4,%5}, {%6,%7}, {%0,%1};"
        : "+r"(c0), "+r"(c1)
        : "r"(a0), "r"(a1), "r"(a2), "r"(a3), "r"(b0), "r"(b1));
}

// ---------------------------------------------------------------------------
// Merged fp32 -> fp16 convert for x, W_in, W_out (one launch)
// ---------------------------------------------------------------------------
#define N4_X  ((size_t)M_DIM * D_DIM / 4)
#define N4_WI ((size_t)2 * D_DIM * D_DIM / 4)
#define N4_WO ((size_t)D_DIM * D_DIM / 4)

__global__ void cvt_all_kernel(const float* __restrict__ x,
                               const float* __restrict__ wi,
                               const float* __restrict__ wo,
                               __half* __restrict__ xh,
                               __half* __restrict__ wih,
                               __half* __restrict__ woh)
{
    size_t i = blockIdx.x * (size_t)blockDim.x + threadIdx.x;
    const float* in; __half* out; size_t j;
    if (i < N4_X)                      { in = x;  out = xh;  j = i; }
    else if (i < N4_X + N4_WI)         { in = wi; out = wih; j = i - N4_X; }
    else if (i < N4_X + N4_WI + N4_WO) { in = wo; out = woh; j = i - N4_X - N4_WI; }
    else return;
    float4 v = ((const float4*)in)[j];
    ((__half2*)out)[2 * j]     = __floats2half2_rn(v.x, v.y);
    ((__half2*)out)[2 * j + 1] = __floats2half2_rn(v.z, v.w);
}

// ---------------------------------------------------------------------------
// fp16-acc GEMM: 256x128 block tile, 8 warps (4M x 2N), warp tile 64x64,
// BK=64, 2-stage double buffer. smem-reads/output-elem = 0.5B (vs 0.75
// for 128x128/32x64), ldsm:MMA = 8:32.
// ---------------------------------------------------------------------------
#define BK        64
#define BM        256
#define BN        128
#define A_TILE_B  (BM * 128)               // 32768
#define W_TILE_B  (BN * 128)               // 16384
#define STAGE_B   (A_TILE_B + W_TILE_B)    // 49152
#define SMEM_GEMM (2 * STAGE_B)            // 98304

__device__ __forceinline__ void load_stage(
    uint32_t sbase, int s, int chunk, int m0, int n0, int tid,
    const __half* __restrict__ A, const __half* __restrict__ W)
{
    const int k0 = chunk * BK;
    uint32_t stA = sbase + s * STAGE_B;
    uint32_t stW = stA + A_TILE_B;

    // A: 256 rows x 8 16B-chunks = 2048 -> 8 per thread
    #pragma unroll
    for (int i = 0; i < 8; i++) {
        int g   = tid + i * 256;
        int row = g >> 3;
        int c16 = g & 7;
        uint32_t so = swz(row * 128 + c16 * 16);
        cpa16(stA + so, A + (size_t)(m0 + row) * KGL + k0 + c16 * 8);
    }
    // W: 128 rows x 8 = 1024 -> 4 per thread
    #pragma unroll
    for (int i = 0; i < 4; i++) {
        int g   = tid + i * 256;
        int row = g >> 3;
        int c16 = g & 7;
        uint32_t so = swz(row * 128 + c16 * 16);
        cpa16(stW + so, W + (size_t)(n0 + row) * KGL + k0 + c16 * 8);
    }
    CP_COMMIT();
}

__global__ __launch_bounds__(256, 2)
void gemm_h16(const __half* __restrict__ A, const __half* __restrict__ W,
              const float* __restrict__ bias, __half* __restrict__ C, int N)
{
    extern __shared__ char smem[];
    const uint32_t sb = s2u(smem);
    const int tid    = threadIdx.x;
    const int lane   = tid & 31;
    const int wid    = tid >> 5;
    const int warp_m = wid & 3;            // 4 x 64 rows
    const int warp_n = wid >> 2;           // 2 x 64 cols
    const int m0 = blockIdx.y * BM;
    const int n0 = blockIdx.x * BN;
    const int NCHUNK = KGL / BK;           // 8

    uint32_t a_off[4], b_off[4];
    #pragma unroll
    for (int mf = 0; mf < 4; mf++) {
        uint32_t row = warp_m * 64 + mf * 16 + (lane & 15);
        a_off[mf] = swz(row * 128 + (lane >> 4) * 16);
    }
    #pragma unroll
    for (int nf2 = 0; nf2 < 4; nf2++) {
        uint32_t row = warp_n * 64 + nf2 * 16 + (lane & 7) + ((lane >> 4) << 3);
        b_off[nf2] = swz(row * 128 + ((lane >> 3) & 1) * 16);
    }

    uint32_t acc[4][8][2];
    #pragma unroll
    for (int i = 0; i < 4; i++)
        #pragma unroll
        for (int j = 0; j < 8; j++) { acc[i][j][0] = 0u; acc[i][j][1] = 0u; }

    load_stage(sb, 0, 0, m0, n0, tid, A, W);
    load_stage(sb, 1, 1, m0, n0, tid, A, W);

    #pragma unroll 1
    for (int c = 0; c < NCHUNK; c++) {
        const int s = c & 1;
        if (c + 1 < NCHUNK) { CP_WAIT1(); } else { CP_WAIT0(); }
        __syncthreads();

        const uint32_t stA = sb + s * STAGE_B;
        const uint32_t stW = stA + A_TILE_B;

        #pragma unroll
        for (int ks = 0; ks < 4; ks++) {
            const uint32_t kx = ks * 32;
            uint32_t af[4][4];
            #pragma unroll
            for (int mf = 0; mf < 4; mf++)
                ldsm4(af[mf][0], af[mf][1], af[mf][2], af[mf][3],
                      stA + (a_off[mf] ^ kx));
            uint32_t bf[8][2];
            #pragma unroll
            for (int nf2 = 0; nf2 < 4; nf2++) {
                uint32_t r0, r1, r2, r3;
                ldsm4(r0, r1, r2, r3, stW + (b_off[nf2] ^ kx));
                bf[nf2 * 2][0] = r0; bf[nf2 * 2][1] = r1;
                bf[nf2 * 2 + 1][0] = r2; bf[nf2 * 2 + 1][1] = r3;
            }
            #pragma unroll
            for (int mf = 0; mf < 4; mf++)
                #pragma unroll
                for (int nf = 0; nf < 8; nf++)
                    mma16816h(acc[mf][nf][0], acc[mf][nf][1],
                              af[mf][0], af[mf][1], af[mf][2], af[mf][3],
                              bf[nf][0], bf[nf][1]);
        }

        __syncthreads();
        if (c + 2 < NCHUNK)
            load_stage(sb, s, c + 2, m0, n0, tid, A, W);
    }

    // Epilogue: add bias (fp16), store fp16
    #pragma unroll
    for (int mf = 0; mf < 4; mf++) {
        int r0 = m0 + warp_m * 64 + mf * 16 + (lane >> 2);
        #pragma unroll
        for (int nf = 0; nf < 8; nf++) {
            int n = n0 + warp_n * 64 + nf * 8 + (lane & 3) * 2;
            __half2 bias2 = __floats2half2_rn(bias[n], bias[n + 1]);
            __half2 v0 = __hadd2(*(__half2*)&acc[mf][nf][0], bias2);
            __half2 v1 = __hadd2(*(__half2*)&acc[mf][nf][1], bias2);
            *(__half2*)(C + (size_t)r0 * N + n)       = v0;
            *(__half2*)(C + (size_t)(r0 + 8) * N + n) = v1;
        }
    }
}

// ---------------------------------------------------------------------------
// Chunked gated recurrence over fp16 zg. 16 chunks x 128 steps, 32-step
// warm-up. Writes h as fp16.
// ---------------------------------------------------------------------------
#define SCAN_CHUNKS 16
#define SCAN_L      (T_DIM / SCAN_CHUNKS)   // 128
#define SCAN_W      32

__global__ __launch_bounds__(256)
void scan_kernel(const float* __restrict__ Avec, const float* __restrict__ Bvec)
{
    int idx = blockIdx.x * blockDim.x + threadIdx.x;
    int d = idx & 511;
    int b = (idx >> 9) & 31;
    int chunk = idx >> 14;

    float a_d = Avec[d];
    float b_d = Bvec[d];
    const __half* zg = g_zgh + (size_t)b * (2 * D_DIM) + d;
    __half* hp = g_hh + (size_t)b * D_DIM + d;
    const size_t zs = (size_t)B_DIM * 2 * D_DIM;
    const size_t hs = (size_t)B_DIM * D_DIM;

    const int t0 = chunk * SCAN_L;
    const int tw = (chunk == 0) ? 0 : t0 - SCAN_W;

    float h = 0.f;
    for (int t = tw; t < t0; t += 8) {
        float zz[8], gg[8];
        #pragma unroll
        for (int i = 0; i < 8; i++) {
            zz[i] = __half2float(zg[(size_t)(t + i) * zs]);
            gg[i] = __half2float(zg[(size_t)(t + i) * zs + D_DIM]);
        }
        #pragma unroll
        for (int i = 0; i < 8; i++) {
            float g = 1.f / (1.f + __expf(-gg[i]));
            h = fmaf(g * a_d, h, b_d * zz[i]);
        }
    }
    for (int t = t0; t < t0 + SCAN_L; t += 8) {
        float zz[8], gg[8];
        #pragma unroll
        for (int i = 0; i < 8; i++) {
            zz[i] = __half2float(zg[(size_t)(t + i) * zs]);
            gg[i] = __half2float(zg[(size_t)(t + i) * zs + D_DIM]);
        }
        #pragma unroll
        for (int i = 0; i < 8; i++) {
            float g = 1.f / (1.f + __expf(-gg[i]));
            h = fmaf(g * a_d, h, b_d * zz[i]);
            hp[(size_t)(t + i) * hs] = __float2half_rn(h);
        }
    }
}

// ---------------------------------------------------------------------------
// LayerNorm(x + proj): x fp32, proj fp16 -> out fp32
// ---------------------------------------------------------------------------
__global__ __launch_bounds__(128)
void ln_kernel(const float* __restrict__ x, const __half* __restrict__ proj,
               const float* __restrict__ gamma, const float* __restrict__ beta,
               float* __restrict__ out)
{
    const size_t r = blockIdx.x;
    const float* xr = x + r * D_DIM;
    const __half* pr = proj + r * D_DIM;
    float* orow = out + r * D_DIM;
    const int t = threadIdx.x;

    float v[4];
    {
        float4 xv = *(const float4*)(xr + t * 4);
        __half2 p0 = *(const __half2*)(pr + t * 4);
        __half2 p1 = *(const __half2*)(pr + t * 4 + 2);
        float2 f0 = __half22float2(p0);
        float2 f1 = __half22float2(p1);
        v[0] = xv.x + f0.x; v[1] = xv.y + f0.y;
        v[2] = xv.z + f1.x; v[3] = xv.w + f1.y;
    }
    float s1 = v[0] + v[1] + v[2] + v[3];
    float s2 = v[0] * v[0] + v[1] * v[1] + v[2] * v[2] + v[3] * v[3];

    #pragma unroll
    for (int off = 16; off; off >>= 1) {
        s1 += __shfl_xor_sync(0xffffffffu, s1, off);
        s2 += __shfl_xor_sync(0xffffffffu, s2, off);
    }
    __shared__ float sh1[4], sh2[4];
    int w = t >> 5;
    if ((t & 31) == 0) { sh1[w] = s1; sh2[w] = s2; }
    __syncthreads();
    s1 = sh1[0] + sh1[1] + sh1[2] + sh1[3];
    s2 = sh2[0] + sh2[1] + sh2[2] + sh2[3];

    float mu  = s1 * (1.f / D_DIM);
    float var = s2 * (1.f / D_DIM) - mu * mu;
    float rs  = rsqrtf(var + 1e-5f);

    float4 o;
    o.x = (v[0] - mu) * rs * gamma[t * 4]     + beta[t * 4];
    o.y = (v[1] - mu) * rs * gamma[t * 4 + 1] + beta[t * 4 + 1];
    o.z = (v[2] - mu) * rs * gamma[t * 4 + 2] + beta[t * 4 + 2];
    o.w = (v[3] - mu) * rs * gamma[t * 4 + 3] + beta[t * 4 + 3];
    *(float4*)(orow + t * 4) = o;
}

// ---------------------------------------------------------------------------
extern "C" void kernel_launch(void* const* d_in, const int* in_sizes, int n_in,
                              void* d_out, int out_size)
{
    const float* x     = (const float*)d_in[0];
    const float* W_in  = (const float*)d_in[1];
    const float* b_in  = (const float*)d_in[2];
    const float* W_out = (const float*)d_in[3];
    const float* b_out = (const float*)d_in[4];
    const float* Avec  = (const float*)d_in[5];
    const float* Bvec  = (const float*)d_in[6];
    const float* gamma = (const float*)d_in[7];
    const float* beta  = (const float*)d_in[8];
    float* out = (float*)d_out;

    __half *zgh, *xh, *ph, *hh, *wih, *woh;
    cudaGetSymbolAddress((void**)&zgh, g_zgh);
    cudaGetSymbolAddress((void**)&xh,  g_xh);
    cudaGetSymbolAddress((void**)&ph,  g_ph);
    cudaGetSymbolAddress((void**)&hh,  g_hh);
    cudaGetSymbolAddress((void**)&wih, g_wih);
    cudaGetSymbolAddress((void**)&woh, g_woh);

    cudaFuncSetAttribute(gemm_h16, cudaFuncAttributeMaxDynamicSharedMemorySize,
                         SMEM_GEMM);

    // Merged converts (x, W_in, W_out -> fp16)
    {
        size_t total = N4_X + N4_WI + N4_WO;
        cvt_all_kernel<<<(unsigned)((total + 255) / 256), 256>>>(
            x, W_in, W_out, xh, wih, woh);
    }

    // GEMM1: zg[M, 2D] = x * W_in^T + b_in  (fp16 acc, fp16 out)
    gemm_h16<<<dim3(2 * D_DIM / BN, M_DIM / BM), 256, SMEM_GEMM>>>(
        xh, wih, b_in, zgh, 2 * D_DIM);

    // Chunked gated scan -> h (fp16)
    scan_kernel<<<(SCAN_CHUNKS * B_DIM * D_DIM) / 256, 256>>>(Avec, Bvec);

    // GEMM2: proj[M, D] = h * W_out^T + b_out  (fp16 acc, fp16 out)
    gemm_h16<<<dim3(D_DIM / BN, M_DIM / BM), 256, SMEM_GEMM>>>(
        hh, woh, b_out, ph, D_DIM);

    // LayerNorm(x + proj) -> out
    ln_kernel<<<M_DIM, 128>>>(x, ph, gamma, beta, out);
}